// round 5
// baseline (speedup 1.0000x reference)
#include <cuda_runtime.h>
#include <cuda_bf16.h>
#include <cstdint>

#define MM 50000
#define EE 800000
#define KK 512
#define NN 128

// ---------------- device scratch (allocation-free rule) ----------------
__device__ float g_x[(size_t)MM * NN];                 // feat @ W (25.6 MB)
__device__ __nv_bfloat16 g_wt0[(size_t)NN * KK];       // W^T bf16 split 0  [n][k]
__device__ __nv_bfloat16 g_wt1[(size_t)NN * KK];       // split 1
__device__ __nv_bfloat16 g_wt2[(size_t)NN * KK];       // split 2

__device__ __forceinline__ uint32_t smem_u32(const void* p) {
    uint32_t a;
    asm("{ .reg .u64 t; cvta.to.shared.u64 t, %1; cvt.u32.u64 %0, t; }" : "=r"(a) : "l"(p));
    return a;
}

// ---------------- W prep: transpose + 3-way bf16 split ----------------
__global__ void prep_w_kernel(const float* __restrict__ W) {
    const int idx = blockIdx.x * blockDim.x + threadIdx.x;   // over N*K = 65536
    if (idx >= NN * KK) return;
    const int n = idx >> 9;          // / KK
    const int k = idx & (KK - 1);
    const float w = W[(size_t)k * NN + n];
    __nv_bfloat16 h0 = __float2bfloat16_rn(w);
    float r = w - __bfloat162float(h0);
    __nv_bfloat16 h1 = __float2bfloat16_rn(r);
    r -= __bfloat162float(h1);
    __nv_bfloat16 h2 = __float2bfloat16_rn(r);
    g_wt0[idx] = h0; g_wt1[idx] = h1; g_wt2[idx] = h2;
}

// ---------------- fp32 -> 3x bf16 split of a pair, packed ----------------
__device__ __forceinline__ void split3_pair(float x0, float x1,
                                            uint32_t &u0, uint32_t &u1, uint32_t &u2) {
    __nv_bfloat16 a0 = __float2bfloat16_rn(x0); float ra = x0 - __bfloat162float(a0);
    __nv_bfloat16 a1 = __float2bfloat16_rn(ra); ra -= __bfloat162float(a1);
    __nv_bfloat16 a2 = __float2bfloat16_rn(ra);
    __nv_bfloat16 b0 = __float2bfloat16_rn(x1); float rb = x1 - __bfloat162float(b0);
    __nv_bfloat16 b1 = __float2bfloat16_rn(rb); rb -= __bfloat162float(b1);
    __nv_bfloat16 b2 = __float2bfloat16_rn(rb);
    u0 = (uint32_t)__bfloat16_as_ushort(a0) | ((uint32_t)__bfloat16_as_ushort(b0) << 16);
    u1 = (uint32_t)__bfloat16_as_ushort(a1) | ((uint32_t)__bfloat16_as_ushort(b1) << 16);
    u2 = (uint32_t)__bfloat16_as_ushort(a2) | ((uint32_t)__bfloat16_as_ushort(b2) << 16);
}

__device__ __forceinline__ void hmma16816(float c[4], const uint32_t a[4],
                                          uint32_t b0, uint32_t b1) {
    asm volatile(
        "mma.sync.aligned.m16n8k16.row.col.f32.bf16.bf16.f32 "
        "{%0,%1,%2,%3}, {%4,%5,%6,%7}, {%8,%9}, {%0,%1,%2,%3};"
        : "+f"(c[0]), "+f"(c[1]), "+f"(c[2]), "+f"(c[3])
        : "r"(a[0]), "r"(a[1]), "r"(a[2]), "r"(a[3]), "r"(b0), "r"(b1));
}

#define LDSM_X4(r, addr) \
    asm volatile("ldmatrix.sync.aligned.m8n8.x4.shared.b16 {%0,%1,%2,%3}, [%4];" \
        : "=r"((r)[0]), "=r"((r)[1]), "=r"((r)[2]), "=r"((r)[3]) : "r"(addr))

// ---------------- GEMM: g_x = feat @ W via HMMA + ldmatrix, 3-split bf16 ----------------
// CTA tile: 128(M) x 128(N=full), K chunks of 32. 256 threads = 8 warps (4x2).
#define BK 32
#define PAD 40                           // 80B row stride -> conflict-free ldmatrix
#define SPLIT_EL (128 * PAD)
#define SPLIT_BYTES (SPLIT_EL * 2)       // 10240
#define A_BYTES (3 * SPLIT_BYTES)
#define SMEM_BYTES (2 * A_BYTES)         // 61440
#define NCH (KK / BK)

__global__ void __launch_bounds__(256, 2)
gemm_tc_kernel(const float* __restrict__ A) {
    extern __shared__ char smem[];
    __nv_bfloat16* Asm = (__nv_bfloat16*)smem;                 // [3][128][PAD]
    __nv_bfloat16* Bsm = (__nv_bfloat16*)(smem + A_BYTES);     // [3][128][PAD]

    const int tid    = threadIdx.x;
    const int lane   = tid & 31;
    const int warp   = tid >> 5;
    const int warp_m = warp >> 1;            // 0..3 -> 32 rows
    const int warp_n = warp & 1;             // 0..1 -> 64 cols
    const int m0     = blockIdx.x * 128;
    const int tr     = lane >> 2;
    const int tc2    = (lane & 3) * 2;

    const uint32_t asm_base = smem_u32(Asm);
    const uint32_t bsm_base = smem_u32(Bsm);
    // ldmatrix lane-address patterns (byte offsets) — mapping validated in R4
    const uint32_t a_lane = (((lane & 15) * PAD) + ((lane >> 4) * 8)) * 2;
    const uint32_t b_lane = ((((lane & 7) + ((lane >> 4) * 8)) * PAD) +
                             (((lane >> 3) & 1) * 8)) * 2;
    const uint32_t a_warp = asm_base + (uint32_t)(warp_m * 32 * PAD * 2) + a_lane;
    const uint32_t b_warp = bsm_base + (uint32_t)(warp_n * 64 * PAD * 2) + b_lane;

    const __nv_bfloat16* wt[3] = { g_wt0, g_wt1, g_wt2 };

    float acc[2][8][4];
    #pragma unroll
    for (int i = 0; i < 2; i++)
        #pragma unroll
        for (int j = 0; j < 8; j++)
            #pragma unroll
            for (int q = 0; q < 4; q++) acc[i][j][q] = 0.f;

    for (int ch = 0; ch < NCH; ch++) {
        // ---- A chunk: 128 x 32 fp32 -> 3 bf16 split tiles (direct, no reg prefetch) ----
        #pragma unroll
        for (int it = 0; it < 4; it++) {
            const int idx = tid + it * 256;        // 0..1023 float4s
            const int row = idx >> 3;
            const int c4  = idx & 7;
            const int gm  = m0 + row;
            float4 v = make_float4(0.f, 0.f, 0.f, 0.f);
            if (gm < MM) v = *(const float4*)(A + (size_t)gm * KK + ch * BK + c4 * 4);
            uint32_t q0, q1, q2, r0, r1, r2;
            split3_pair(v.x, v.y, q0, q1, q2);
            split3_pair(v.z, v.w, r0, r1, r2);
            const int base = row * PAD + c4 * 4;
            *(uint2*)&Asm[0 * SPLIT_EL + base] = make_uint2(q0, r0);
            *(uint2*)&Asm[1 * SPLIT_EL + base] = make_uint2(q1, r1);
            *(uint2*)&Asm[2 * SPLIT_EL + base] = make_uint2(q2, r2);
        }
        // ---- B chunk: 3 splits x [128 n][32 k] bf16 (L2-hot) ----
        #pragma unroll
        for (int s = 0; s < 3; s++) {
            #pragma unroll
            for (int it = 0; it < 2; it++) {
                const int idx = tid + it * 256;    // 0..511 16B-pieces
                const int n   = idx >> 2;
                const int kq  = idx & 3;
                const float4 v = *(const float4*)(wt[s] + (size_t)n * KK + ch * BK + kq * 8);
                *(float4*)&Bsm[s * SPLIT_EL + n * PAD + kq * 8] = v;
            }
        }
        __syncthreads();

        // ---- compute: 2 k16-steps; A-split hoisted, products (i,j) with i+j<=2 ----
        #pragma unroll
        for (int ks = 0; ks < 2; ks++) {
            #pragma unroll
            for (int i = 0; i < 3; i++) {
                const uint32_t a_base = a_warp + (uint32_t)(i * SPLIT_BYTES + ks * 32);
                uint32_t am[2][4];
                LDSM_X4(am[0], a_base);
                LDSM_X4(am[1], a_base + 16 * PAD * 2);
                #pragma unroll
                for (int j = 0; j < 3; j++) {
                    if (i + j > 2) continue;
                    const uint32_t b_base = b_warp + (uint32_t)(j * SPLIT_BYTES + ks * 32);
                    #pragma unroll
                    for (int nt2 = 0; nt2 < 4; nt2++) {
                        uint32_t b[4];
                        LDSM_X4(b, b_base + (uint32_t)(nt2 * 16 * PAD * 2));
                        hmma16816(acc[0][nt2 * 2],     am[0], b[0], b[1]);
                        hmma16816(acc[0][nt2 * 2 + 1], am[0], b[2], b[3]);
                        hmma16816(acc[1][nt2 * 2],     am[1], b[0], b[1]);
                        hmma16816(acc[1][nt2 * 2 + 1], am[1], b[2], b[3]);
                    }
                }
            }
        }
        __syncthreads();
    }

    // ---- epilogue: direct STG.64 of fragment pairs ----
    #pragma unroll
    for (int mt = 0; mt < 2; mt++) {
        const int r = m0 + warp_m * 32 + mt * 16 + tr;
        #pragma unroll
        for (int nt = 0; nt < 8; nt++) {
            const int c = warp_n * 64 + nt * 8 + tc2;
            if (r < MM)
                *(float2*)&g_x[(size_t)r * NN + c] =
                    make_float2(acc[mt][nt][0], acc[mt][nt][1]);
            if (r + 8 < MM)
                *(float2*)&g_x[(size_t)(r + 8) * NN + c] =
                    make_float2(acc[mt][nt][2], acc[mt][nt][3]);
        }
    }
}

// ---------------- SpMM + multispike: warp per row, inline row-bound search ----------------
__device__ __forceinline__ float mspike(float a) {
    return floorf(fminf(fmaxf(4.0f * a, 0.0f), 4.0f) + 0.5f) * 0.25f;
}

__global__ __launch_bounds__(256)
void spmm_kernel(const int* __restrict__ rows, const int* __restrict__ cols,
                 const float* __restrict__ ew, float* __restrict__ out) {
    const int wid  = threadIdx.x >> 5;
    const int lane = threadIdx.x & 31;
    const int row  = blockIdx.x * 8 + wid;
    if (row >= MM) return;

    // lanes 0/1 binary-search the CSR bounds (rows sorted), broadcast via shfl
    int bound = 0;
    if (lane < 2) {
        const int target = row + lane;
        int lo = 0, hi = EE;
        while (lo < hi) {
            const int mid = (lo + hi) >> 1;
            if (rows[mid] < target) lo = mid + 1; else hi = mid;
        }
        bound = lo;
    }
    const int s = __shfl_sync(0xffffffffu, bound, 0);
    const int e = __shfl_sync(0xffffffffu, bound, 1);

    const float4* xb = (const float4*)g_x;
    float4 a0 = make_float4(0.f,0.f,0.f,0.f), a1 = a0, a2 = a0, a3 = a0;
    int i = s;
    for (; i + 4 <= e; i += 4) {
        const int c0 = cols[i], c1 = cols[i+1], c2 = cols[i+2], c3 = cols[i+3];
        const float w0 = ew[i], w1 = ew[i+1], w2 = ew[i+2], w3 = ew[i+3];
        const float4 v0 = xb[c0 * 32 + lane];
        const float4 v1 = xb[c1 * 32 + lane];
        const float4 v2 = xb[c2 * 32 + lane];
        const float4 v3 = xb[c3 * 32 + lane];
        a0.x = fmaf(w0, v0.x, a0.x); a0.y = fmaf(w0, v0.y, a0.y);
        a0.z = fmaf(w0, v0.z, a0.z); a0.w = fmaf(w0, v0.w, a0.w);
        a1.x = fmaf(w1, v1.x, a1.x); a1.y = fmaf(w1, v1.y, a1.y);
        a1.z = fmaf(w1, v1.z, a1.z); a1.w = fmaf(w1, v1.w, a1.w);
        a2.x = fmaf(w2, v2.x, a2.x); a2.y = fmaf(w2, v2.y, a2.y);
        a2.z = fmaf(w2, v2.z, a2.z); a2.w = fmaf(w2, v2.w, a2.w);
        a3.x = fmaf(w3, v3.x, a3.x); a3.y = fmaf(w3, v3.y, a3.y);
        a3.z = fmaf(w3, v3.z, a3.z); a3.w = fmaf(w3, v3.w, a3.w);
    }
    for (; i < e; i++) {
        const int c = cols[i];
        const float w = ew[i];
        const float4 v = xb[c * 32 + lane];
        a0.x = fmaf(w, v.x, a0.x); a0.y = fmaf(w, v.y, a0.y);
        a0.z = fmaf(w, v.z, a0.z); a0.w = fmaf(w, v.w, a0.w);
    }
    float4 t;
    t.x = mspike((a0.x + a1.x) + (a2.x + a3.x));
    t.y = mspike((a0.y + a1.y) + (a2.y + a3.y));
    t.z = mspike((a0.z + a1.z) + (a2.z + a3.z));
    t.w = mspike((a0.w + a1.w) + (a2.w + a3.w));
    ((float4*)out)[(size_t)row * 32 + lane] = t;
}

// ---------------- launch ----------------
extern "C" void kernel_launch(void* const* d_in, const int* in_sizes, int n_in,
                              void* d_out, int out_size) {
    const float* feat   = (const float*)d_in[0];
    const float* weight = (const float*)d_in[1];
    const int*   rows   = (const int*)d_in[2];
    const int*   cols   = (const int*)d_in[3];
    const float* ew     = (const float*)d_in[4];
    float* out = (float*)d_out;

    cudaFuncSetAttribute(gemm_tc_kernel,
                         cudaFuncAttributeMaxDynamicSharedMemorySize, SMEM_BYTES);

    prep_w_kernel<<<(NN * KK + 255) / 256, 256>>>(weight);
    gemm_tc_kernel<<<(MM + 127) / 128, 256, SMEM_BYTES>>>(feat);
    spmm_kernel<<<(MM + 7) / 8, 256>>>(rows, cols, ew, out);
}

// round 8
// speedup vs baseline: 1.0093x; 1.0093x over previous
#include <cuda_runtime.h>
#include <cuda_bf16.h>
#include <cstdint>

#define MM 50000
#define EE 800000
#define KK 512
#define NN 128

// ---------------- device scratch (allocation-free rule) ----------------
__device__ float g_x[(size_t)MM * NN];                 // feat @ W (25.6 MB)
__device__ __nv_bfloat16 g_wt0[(size_t)NN * KK];       // W^T bf16 split 0  [n][k]
__device__ __nv_bfloat16 g_wt1[(size_t)NN * KK];       // split 1
__device__ __nv_bfloat16 g_wt2[(size_t)NN * KK];       // split 2

// ---------------- W prep: transpose + 3-way bf16 split ----------------
__global__ void prep_w_kernel(const float* __restrict__ W) {
    const int idx = blockIdx.x * blockDim.x + threadIdx.x;   // over N*K = 65536
    if (idx >= NN * KK) return;
    const int n = idx >> 9;          // / KK
    const int k = idx & (KK - 1);
    const float w = W[(size_t)k * NN + n];
    __nv_bfloat16 h0 = __float2bfloat16_rn(w);
    float r = w - __bfloat162float(h0);
    __nv_bfloat16 h1 = __float2bfloat16_rn(r);
    r -= __bfloat162float(h1);
    __nv_bfloat16 h2 = __float2bfloat16_rn(r);
    g_wt0[idx] = h0; g_wt1[idx] = h1; g_wt2[idx] = h2;
}

// ---------------- fp32 -> 3x bf16 split of a pair, packed ----------------
__device__ __forceinline__ void split3_pair(float x0, float x1,
                                            uint32_t &u0, uint32_t &u1, uint32_t &u2) {
    __nv_bfloat16 a0 = __float2bfloat16_rn(x0); float ra = x0 - __bfloat162float(a0);
    __nv_bfloat16 a1 = __float2bfloat16_rn(ra); ra -= __bfloat162float(a1);
    __nv_bfloat16 a2 = __float2bfloat16_rn(ra);
    __nv_bfloat16 b0 = __float2bfloat16_rn(x1); float rb = x1 - __bfloat162float(b0);
    __nv_bfloat16 b1 = __float2bfloat16_rn(rb); rb -= __bfloat162float(b1);
    __nv_bfloat16 b2 = __float2bfloat16_rn(rb);
    u0 = (uint32_t)__bfloat16_as_ushort(a0) | ((uint32_t)__bfloat16_as_ushort(b0) << 16);
    u1 = (uint32_t)__bfloat16_as_ushort(a1) | ((uint32_t)__bfloat16_as_ushort(b1) << 16);
    u2 = (uint32_t)__bfloat16_as_ushort(a2) | ((uint32_t)__bfloat16_as_ushort(b2) << 16);
}

__device__ __forceinline__ void hmma16816(float c[4], const uint32_t a[4],
                                          uint32_t b0, uint32_t b1) {
    asm volatile(
        "mma.sync.aligned.m16n8k16.row.col.f32.bf16.bf16.f32 "
        "{%0,%1,%2,%3}, {%4,%5,%6,%7}, {%8,%9}, {%0,%1,%2,%3};"
        : "+f"(c[0]), "+f"(c[1]), "+f"(c[2]), "+f"(c[3])
        : "r"(a[0]), "r"(a[1]), "r"(a[2]), "r"(a[3]), "r"(b0), "r"(b1));
}

// ---------------- GEMM: g_x = feat @ W via HMMA, 3-split bf16 (R3 base) ----------------
// CTA tile: 128(M) x 128(N=full), K chunks of 32. 256 threads = 8 warps (4x2).
// smem: A splits [3][128][PAD] bf16, B splits [3][128][PAD] bf16 ([n][k] layout).
#define BK 32
#define PAD 40                      // stride 40 el = 80B = 20 banks -> conflict-free scalar LDS
#define SPLIT_EL (128 * PAD)
#define A_BYTES (3 * SPLIT_EL * 2)
#define SMEM_BYTES (2 * A_BYTES)    // 61440
#define NCH (KK / BK)

__global__ void __launch_bounds__(256, 2)
gemm_tc_kernel(const float* __restrict__ A) {
    extern __shared__ char smem[];
    __nv_bfloat16* Asm = (__nv_bfloat16*)smem;                 // [3][128][PAD]
    __nv_bfloat16* Bsm = (__nv_bfloat16*)(smem + A_BYTES);     // [3][128][PAD]

    const int tid    = threadIdx.x;
    const int lane   = tid & 31;
    const int warp   = tid >> 5;
    const int warp_m = warp >> 1;            // 0..3  -> 32 rows each
    const int warp_n = warp & 1;             // 0..1  -> 64 cols each
    const int m0     = blockIdx.x * 128;
    const int tr     = lane >> 2;            // 0..7
    const int tc2    = (lane & 3) * 2;       // 0,2,4,6

    const __nv_bfloat16* wt[3] = { g_wt0, g_wt1, g_wt2 };

    float acc[2][8][4];
    #pragma unroll
    for (int i = 0; i < 2; i++)
        #pragma unroll
        for (int j = 0; j < 8; j++)
            #pragma unroll
            for (int q = 0; q < 4; q++) acc[i][j][q] = 0.f;

    for (int ch = 0; ch < NCH; ch++) {
        // ---- A chunk: 128 x 32 fp32 -> 3 bf16 split tiles ----
        #pragma unroll
        for (int it = 0; it < 4; it++) {
            const int idx = tid + it * 256;        // 0..1023 float4s
            const int row = idx >> 3;
            const int c4  = idx & 7;               // float4 within 32 cols
            const int gm  = m0 + row;
            float4 v = make_float4(0.f, 0.f, 0.f, 0.f);
            if (gm < MM) v = *(const float4*)(A + (size_t)gm * KK + ch * BK + c4 * 4);
            uint32_t q0, q1, q2, r0, r1, r2;
            split3_pair(v.x, v.y, q0, q1, q2);
            split3_pair(v.z, v.w, r0, r1, r2);
            const int base = row * PAD + c4 * 4;
            *(uint2*)&Asm[0 * SPLIT_EL + base] = make_uint2(q0, r0);
            *(uint2*)&Asm[1 * SPLIT_EL + base] = make_uint2(q1, r1);
            *(uint2*)&Asm[2 * SPLIT_EL + base] = make_uint2(q2, r2);
        }
        // ---- B chunk: 3 splits x [128 n][32 k] bf16 (L2-hot) ----
        #pragma unroll
        for (int s = 0; s < 3; s++) {
            #pragma unroll
            for (int it = 0; it < 2; it++) {
                const int idx = tid + it * 256;    // 0..511 16B-pieces
                const int n   = idx >> 2;
                const int kq  = idx & 3;           // 8-bf16 group
                const float4 v = *(const float4*)(wt[s] + (size_t)n * KK + ch * BK + kq * 8);
                *(float4*)&Bsm[s * SPLIT_EL + n * PAD + kq * 8] = v;
            }
        }
        __syncthreads();

        // ---- compute: 2 k16-steps; A-fragment hoisted per a-split (scalar LDS) ----
        #pragma unroll
        for (int ks = 0; ks < 2; ks++) {
            const int k0 = ks * 16;
            #pragma unroll
            for (int i = 0; i < 3; i++) {
                const __nv_bfloat16* Ab = Asm + i * SPLIT_EL;
                uint32_t am[2][4];
                #pragma unroll
                for (int mt = 0; mt < 2; mt++) {
                    const int r = warp_m * 32 + mt * 16 + tr;
                    am[mt][0] = *(const uint32_t*)&Ab[(r    ) * PAD + k0 + tc2    ];
                    am[mt][1] = *(const uint32_t*)&Ab[(r + 8) * PAD + k0 + tc2    ];
                    am[mt][2] = *(const uint32_t*)&Ab[(r    ) * PAD + k0 + tc2 + 8];
                    am[mt][3] = *(const uint32_t*)&Ab[(r + 8) * PAD + k0 + tc2 + 8];
                }
                #pragma unroll
                for (int j = 0; j < 3 - i; j++) {   // i+j <= 2
                    const __nv_bfloat16* Bb = Bsm + j * SPLIT_EL;
                    #pragma unroll
                    for (int nt = 0; nt < 8; nt++) {
                        const int n = warp_n * 64 + nt * 8 + tr;
                        const uint32_t b0 = *(const uint32_t*)&Bb[n * PAD + k0 + tc2    ];
                        const uint32_t b1 = *(const uint32_t*)&Bb[n * PAD + k0 + tc2 + 8];
                        hmma16816(acc[0][nt], am[0], b0, b1);
                        hmma16816(acc[1][nt], am[1], b0, b1);
                    }
                }
            }
        }
        __syncthreads();
    }

    // ---- epilogue: direct STG.64 of fragment pairs ----
    #pragma unroll
    for (int mt = 0; mt < 2; mt++) {
        const int r = m0 + warp_m * 32 + mt * 16 + tr;
        #pragma unroll
        for (int nt = 0; nt < 8; nt++) {
            const int c = warp_n * 64 + nt * 8 + tc2;
            if (r < MM)
                *(float2*)&g_x[(size_t)r * NN + c] =
                    make_float2(acc[mt][nt][0], acc[mt][nt][1]);
            if (r + 8 < MM)
                *(float2*)&g_x[(size_t)(r + 8) * NN + c] =
                    make_float2(acc[mt][nt][2], acc[mt][nt][3]);
        }
    }
}

// ---------------- SpMM + multispike: warp per row, inline row-bound search ----------------
__device__ __forceinline__ float mspike(float a) {
    return floorf(fminf(fmaxf(4.0f * a, 0.0f), 4.0f) + 0.5f) * 0.25f;
}

__global__ __launch_bounds__(256)
void spmm_kernel(const int* __restrict__ rows, const int* __restrict__ cols,
                 const float* __restrict__ ew, float* __restrict__ out) {
    const int wid  = threadIdx.x >> 5;
    const int lane = threadIdx.x & 31;
    const int row  = blockIdx.x * 8 + wid;
    if (row >= MM) return;

    // lanes 0/1 binary-search the CSR bounds (rows sorted), broadcast via shfl
    int bound = 0;
    if (lane < 2) {
        const int target = row + lane;
        int lo = 0, hi = EE;
        while (lo < hi) {
            const int mid = (lo + hi) >> 1;
            if (rows[mid] < target) lo = mid + 1; else hi = mid;
        }
        bound = lo;
    }
    const int s = __shfl_sync(0xffffffffu, bound, 0);
    const int e = __shfl_sync(0xffffffffu, bound, 1);

    const float4* xb = (const float4*)g_x;
    float4 a0 = make_float4(0.f,0.f,0.f,0.f), a1 = a0, a2 = a0, a3 = a0;
    int i = s;
    for (; i + 4 <= e; i += 4) {
        const int c0 = cols[i], c1 = cols[i+1], c2 = cols[i+2], c3 = cols[i+3];
        const float w0 = ew[i], w1 = ew[i+1], w2 = ew[i+2], w3 = ew[i+3];
        const float4 v0 = xb[c0 * 32 + lane];
        const float4 v1 = xb[c1 * 32 + lane];
        const float4 v2 = xb[c2 * 32 + lane];
        const float4 v3 = xb[c3 * 32 + lane];
        a0.x = fmaf(w0, v0.x, a0.x); a0.y = fmaf(w0, v0.y, a0.y);
        a0.z = fmaf(w0, v0.z, a0.z); a0.w = fmaf(w0, v0.w, a0.w);
        a1.x = fmaf(w1, v1.x, a1.x); a1.y = fmaf(w1, v1.y, a1.y);
        a1.z = fmaf(w1, v1.z, a1.z); a1.w = fmaf(w1, v1.w, a1.w);
        a2.x = fmaf(w2, v2.x, a2.x); a2.y = fmaf(w2, v2.y, a2.y);
        a2.z = fmaf(w2, v2.z, a2.z); a2.w = fmaf(w2, v2.w, a2.w);
        a3.x = fmaf(w3, v3.x, a3.x); a3.y = fmaf(w3, v3.y, a3.y);
        a3.z = fmaf(w3, v3.z, a3.z); a3.w = fmaf(w3, v3.w, a3.w);
    }
    for (; i < e; i++) {
        const int c = cols[i];
        const float w = ew[i];
        const float4 v = xb[c * 32 + lane];
        a0.x = fmaf(w, v.x, a0.x); a0.y = fmaf(w, v.y, a0.y);
        a0.z = fmaf(w, v.z, a0.z); a0.w = fmaf(w, v.w, a0.w);
    }
    float4 t;
    t.x = mspike((a0.x + a1.x) + (a2.x + a3.x));
    t.y = mspike((a0.y + a1.y) + (a2.y + a3.y));
    t.z = mspike((a0.z + a1.z) + (a2.z + a3.z));
    t.w = mspike((a0.w + a1.w) + (a2.w + a3.w));
    ((float4*)out)[(size_t)row * 32 + lane] = t;
}

// ---------------- launch ----------------
extern "C" void kernel_launch(void* const* d_in, const int* in_sizes, int n_in,
                              void* d_out, int out_size) {
    const float* feat   = (const float*)d_in[0];
    const float* weight = (const float*)d_in[1];
    const int*   rows   = (const int*)d_in[2];
    const int*   cols   = (const int*)d_in[3];
    const float* ew     = (const float*)d_in[4];
    float* out = (float*)d_out;

    cudaFuncSetAttribute(gemm_tc_kernel,
                         cudaFuncAttributeMaxDynamicSharedMemorySize, SMEM_BYTES);

    prep_w_kernel<<<(NN * KK + 255) / 256, 256>>>(weight);
    gemm_tc_kernel<<<(MM + 127) / 128, 256, SMEM_BYTES>>>(feat);
    spmm_kernel<<<(MM + 7) / 8, 256>>>(rows, cols, ew, out);
}

// round 9
// speedup vs baseline: 1.1317x; 1.1213x over previous
#include <cuda_runtime.h>
#include <cuda_bf16.h>
#include <cstdint>

#define MM 50000
#define EE 800000
#define KK 512
#define NN 128

// ---------------- device scratch (allocation-free rule) ----------------
__device__ float g_x[(size_t)MM * NN];                 // feat @ W (25.6 MB)
__device__ int   g_rowptr[MM + 1];
__device__ __nv_bfloat16 g_wt0[(size_t)NN * KK];       // W^T bf16 split 0  [n][k]
__device__ __nv_bfloat16 g_wt1[(size_t)NN * KK];       // split 1
__device__ __nv_bfloat16 g_wt2[(size_t)NN * KK];       // split 2

// ---------------- fused prep: W transpose+split  AND  rowptr search ----------------
// Blocks [0, 256): prep_w over N*K = 65536 elements.
// Blocks [256, 256+196): rowptr binary search over MM+1 targets (wide MLP).
#define PREP_BLOCKS 256
#define ROWPTR_BLOCKS ((MM + 1 + 255) / 256)

__global__ void prep_kernel(const float* __restrict__ W, const int* __restrict__ rows) {
    if (blockIdx.x < PREP_BLOCKS) {
        const int idx = blockIdx.x * 256 + threadIdx.x;      // over N*K
        if (idx >= NN * KK) return;
        const int n = idx >> 9;          // / KK
        const int k = idx & (KK - 1);
        const float w = W[(size_t)k * NN + n];
        __nv_bfloat16 h0 = __float2bfloat16_rn(w);
        float r = w - __bfloat162float(h0);
        __nv_bfloat16 h1 = __float2bfloat16_rn(r);
        r -= __bfloat162float(h1);
        __nv_bfloat16 h2 = __float2bfloat16_rn(r);
        g_wt0[idx] = h0; g_wt1[idx] = h1; g_wt2[idx] = h2;
    } else {
        const int i = (blockIdx.x - PREP_BLOCKS) * 256 + threadIdx.x;
        if (i > MM) return;
        int lo = 0, hi = EE;
        while (lo < hi) {
            const int mid = (lo + hi) >> 1;
            if (rows[mid] < i) lo = mid + 1; else hi = mid;
        }
        g_rowptr[i] = lo;
    }
}

// ---------------- fp32 -> 3x bf16 split of a pair, packed ----------------
__device__ __forceinline__ void split3_pair(float x0, float x1,
                                            uint32_t &u0, uint32_t &u1, uint32_t &u2) {
    __nv_bfloat16 a0 = __float2bfloat16_rn(x0); float ra = x0 - __bfloat162float(a0);
    __nv_bfloat16 a1 = __float2bfloat16_rn(ra); ra -= __bfloat162float(a1);
    __nv_bfloat16 a2 = __float2bfloat16_rn(ra);
    __nv_bfloat16 b0 = __float2bfloat16_rn(x1); float rb = x1 - __bfloat162float(b0);
    __nv_bfloat16 b1 = __float2bfloat16_rn(rb); rb -= __bfloat162float(b1);
    __nv_bfloat16 b2 = __float2bfloat16_rn(rb);
    u0 = (uint32_t)__bfloat16_as_ushort(a0) | ((uint32_t)__bfloat16_as_ushort(b0) << 16);
    u1 = (uint32_t)__bfloat16_as_ushort(a1) | ((uint32_t)__bfloat16_as_ushort(b1) << 16);
    u2 = (uint32_t)__bfloat16_as_ushort(a2) | ((uint32_t)__bfloat16_as_ushort(b2) << 16);
}

__device__ __forceinline__ void hmma16816(float c[4], const uint32_t a[4],
                                          uint32_t b0, uint32_t b1) {
    asm volatile(
        "mma.sync.aligned.m16n8k16.row.col.f32.bf16.bf16.f32 "
        "{%0,%1,%2,%3}, {%4,%5,%6,%7}, {%8,%9}, {%0,%1,%2,%3};"
        : "+f"(c[0]), "+f"(c[1]), "+f"(c[2]), "+f"(c[3])
        : "r"(a[0]), "r"(a[1]), "r"(a[2]), "r"(a[3]), "r"(b0), "r"(b1));
}

// ---------------- GEMM: g_x = feat @ W via HMMA, 3-split bf16 ----------------
// CTA tile: 128(M) x 128(N=full), K chunks of 32. 256 threads = 8 warps (4x2).
#define BK 32
#define PAD 40                      // stride 40 el = 80B = 20 banks -> conflict-free scalar LDS
#define SPLIT_EL (128 * PAD)
#define A_BYTES (3 * SPLIT_EL * 2)
#define SMEM_BYTES (2 * A_BYTES)    // 61440
#define NCH (KK / BK)

__global__ void __launch_bounds__(256, 2)
gemm_tc_kernel(const float* __restrict__ A) {
    extern __shared__ char smem[];
    __nv_bfloat16* Asm = (__nv_bfloat16*)smem;                 // [3][128][PAD]
    __nv_bfloat16* Bsm = (__nv_bfloat16*)(smem + A_BYTES);     // [3][128][PAD]

    const int tid    = threadIdx.x;
    const int lane   = tid & 31;
    const int warp   = tid >> 5;
    const int warp_m = warp >> 1;            // 0..3  -> 32 rows each
    const int warp_n = warp & 1;             // 0..1  -> 64 cols each
    const int m0     = blockIdx.x * 128;
    const int tr     = lane >> 2;            // 0..7
    const int tc2    = (lane & 3) * 2;       // 0,2,4,6

    const __nv_bfloat16* wt[3] = { g_wt0, g_wt1, g_wt2 };

    float acc[2][8][4];
    #pragma unroll
    for (int i = 0; i < 2; i++)
        #pragma unroll
        for (int j = 0; j < 8; j++)
            #pragma unroll
            for (int q = 0; q < 4; q++) acc[i][j][q] = 0.f;

    for (int ch = 0; ch < NCH; ch++) {
        // ---- A chunk: 128 x 32 fp32 -> 3 bf16 split tiles ----
        #pragma unroll
        for (int it = 0; it < 4; it++) {
            const int idx = tid + it * 256;        // 0..1023 float4s
            const int row = idx >> 3;
            const int c4  = idx & 7;               // float4 within 32 cols
            const int gm  = m0 + row;
            float4 v = make_float4(0.f, 0.f, 0.f, 0.f);
            if (gm < MM) v = *(const float4*)(A + (size_t)gm * KK + ch * BK + c4 * 4);
            uint32_t q0, q1, q2, r0, r1, r2;
            split3_pair(v.x, v.y, q0, q1, q2);
            split3_pair(v.z, v.w, r0, r1, r2);
            const int base = row * PAD + c4 * 4;
            *(uint2*)&Asm[0 * SPLIT_EL + base] = make_uint2(q0, r0);
            *(uint2*)&Asm[1 * SPLIT_EL + base] = make_uint2(q1, r1);
            *(uint2*)&Asm[2 * SPLIT_EL + base] = make_uint2(q2, r2);
        }
        // ---- B chunk: 3 splits x [128 n][32 k] bf16 (L2-hot) ----
        #pragma unroll
        for (int s = 0; s < 3; s++) {
            #pragma unroll
            for (int it = 0; it < 2; it++) {
                const int idx = tid + it * 256;    // 0..511 16B-pieces
                const int n   = idx >> 2;
                const int kq  = idx & 3;           // 8-bf16 group
                const float4 v = *(const float4*)(wt[s] + (size_t)n * KK + ch * BK + kq * 8);
                *(float4*)&Bsm[s * SPLIT_EL + n * PAD + kq * 8] = v;
            }
        }
        __syncthreads();

        // ---- compute: 2 k16-steps; A-fragment hoisted per a-split (scalar LDS) ----
        #pragma unroll
        for (int ks = 0; ks < 2; ks++) {
            const int k0 = ks * 16;
            #pragma unroll
            for (int i = 0; i < 3; i++) {
                const __nv_bfloat16* Ab = Asm + i * SPLIT_EL;
                uint32_t am[2][4];
                #pragma unroll
                for (int mt = 0; mt < 2; mt++) {
                    const int r = warp_m * 32 + mt * 16 + tr;
                    am[mt][0] = *(const uint32_t*)&Ab[(r    ) * PAD + k0 + tc2    ];
                    am[mt][1] = *(const uint32_t*)&Ab[(r + 8) * PAD + k0 + tc2    ];
                    am[mt][2] = *(const uint32_t*)&Ab[(r    ) * PAD + k0 + tc2 + 8];
                    am[mt][3] = *(const uint32_t*)&Ab[(r + 8) * PAD + k0 + tc2 + 8];
                }
                #pragma unroll
                for (int j = 0; j < 3 - i; j++) {   // i+j <= 2
                    const __nv_bfloat16* Bb = Bsm + j * SPLIT_EL;
                    #pragma unroll
                    for (int nt = 0; nt < 8; nt++) {
                        const int n = warp_n * 64 + nt * 8 + tr;
                        const uint32_t b0 = *(const uint32_t*)&Bb[n * PAD + k0 + tc2    ];
                        const uint32_t b1 = *(const uint32_t*)&Bb[n * PAD + k0 + tc2 + 8];
                        hmma16816(acc[0][nt], am[0], b0, b1);
                        hmma16816(acc[1][nt], am[1], b0, b1);
                    }
                }
            }
        }
        __syncthreads();
    }

    // ---- epilogue: direct STG.64 of fragment pairs ----
    #pragma unroll
    for (int mt = 0; mt < 2; mt++) {
        const int r = m0 + warp_m * 32 + mt * 16 + tr;
        #pragma unroll
        for (int nt = 0; nt < 8; nt++) {
            const int c = warp_n * 64 + nt * 8 + tc2;
            if (r < MM)
                *(float2*)&g_x[(size_t)r * NN + c] =
                    make_float2(acc[mt][nt][0], acc[mt][nt][1]);
            if (r + 8 < MM)
                *(float2*)&g_x[(size_t)(r + 8) * NN + c] =
                    make_float2(acc[mt][nt][2], acc[mt][nt][3]);
        }
    }
}

// ---------------- SpMM + multispike: warp per row, float4 lanes ----------------
__device__ __forceinline__ float mspike(float a) {
    return floorf(fminf(fmaxf(4.0f * a, 0.0f), 4.0f) + 0.5f) * 0.25f;
}

__global__ __launch_bounds__(256)
void spmm_kernel(const int* __restrict__ cols, const float* __restrict__ ew,
                 float* __restrict__ out) {
    const int wid  = threadIdx.x >> 5;
    const int lane = threadIdx.x & 31;
    const int row  = blockIdx.x * 8 + wid;
    if (row >= MM) return;
    const int s = g_rowptr[row];
    const int e = g_rowptr[row + 1];
    const float4* xb = (const float4*)g_x;

    float4 a0 = make_float4(0.f,0.f,0.f,0.f), a1 = a0, a2 = a0, a3 = a0;
    int i = s;
    for (; i + 4 <= e; i += 4) {
        const int c0 = cols[i], c1 = cols[i+1], c2 = cols[i+2], c3 = cols[i+3];
        const float w0 = ew[i], w1 = ew[i+1], w2 = ew[i+2], w3 = ew[i+3];
        const float4 v0 = xb[c0 * 32 + lane];
        const float4 v1 = xb[c1 * 32 + lane];
        const float4 v2 = xb[c2 * 32 + lane];
        const float4 v3 = xb[c3 * 32 + lane];
        a0.x = fmaf(w0, v0.x, a0.x); a0.y = fmaf(w0, v0.y, a0.y);
        a0.z = fmaf(w0, v0.z, a0.z); a0.w = fmaf(w0, v0.w, a0.w);
        a1.x = fmaf(w1, v1.x, a1.x); a1.y = fmaf(w1, v1.y, a1.y);
        a1.z = fmaf(w1, v1.z, a1.z); a1.w = fmaf(w1, v1.w, a1.w);
        a2.x = fmaf(w2, v2.x, a2.x); a2.y = fmaf(w2, v2.y, a2.y);
        a2.z = fmaf(w2, v2.z, a2.z); a2.w = fmaf(w2, v2.w, a2.w);
        a3.x = fmaf(w3, v3.x, a3.x); a3.y = fmaf(w3, v3.y, a3.y);
        a3.z = fmaf(w3, v3.z, a3.z); a3.w = fmaf(w3, v3.w, a3.w);
    }
    for (; i < e; i++) {
        const int c = cols[i];
        const float w = ew[i];
        const float4 v = xb[c * 32 + lane];
        a0.x = fmaf(w, v.x, a0.x); a0.y = fmaf(w, v.y, a0.y);
        a0.z = fmaf(w, v.z, a0.z); a0.w = fmaf(w, v.w, a0.w);
    }
    float4 t;
    t.x = mspike((a0.x + a1.x) + (a2.x + a3.x));
    t.y = mspike((a0.y + a1.y) + (a2.y + a3.y));
    t.z = mspike((a0.z + a1.z) + (a2.z + a3.z));
    t.w = mspike((a0.w + a1.w) + (a2.w + a3.w));
    ((float4*)out)[(size_t)row * 32 + lane] = t;
}

// ---------------- launch ----------------
extern "C" void kernel_launch(void* const* d_in, const int* in_sizes, int n_in,
                              void* d_out, int out_size) {
    const float* feat   = (const float*)d_in[0];
    const float* weight = (const float*)d_in[1];
    const int*   rows   = (const int*)d_in[2];
    const int*   cols   = (const int*)d_in[3];
    const float* ew     = (const float*)d_in[4];
    float* out = (float*)d_out;

    cudaFuncSetAttribute(gemm_tc_kernel,
                         cudaFuncAttributeMaxDynamicSharedMemorySize, SMEM_BYTES);

    prep_kernel<<<PREP_BLOCKS + ROWPTR_BLOCKS, 256>>>(weight, rows);
    gemm_tc_kernel<<<(MM + 127) / 128, 256, SMEM_BYTES>>>(feat);
    spmm_kernel<<<(MM + 7) / 8, 256>>>(cols, ew, out);
}

// round 10
// speedup vs baseline: 1.1687x; 1.0326x over previous
#include <cuda_runtime.h>
#include <cuda_bf16.h>
#include <cstdint>

#define MM 50000
#define EE 800000
#define KK 512
#define NN 128

// ---------------- device scratch (allocation-free rule) ----------------
__device__ float g_x[(size_t)MM * NN];                 // feat @ W (25.6 MB)
__device__ int   g_rowptr[MM + 1];
__device__ __nv_bfloat16 g_wt0[(size_t)NN * KK];       // W^T bf16 split 0  [n][k]
__device__ __nv_bfloat16 g_wt1[(size_t)NN * KK];       // split 1
__device__ __nv_bfloat16 g_wt2[(size_t)NN * KK];       // split 2

// ---------------- fused prep: W transpose+split AND rowptr boundary-scan ----------------
// Blocks [0, 256): W split over N*K = 65536 elements.
// Blocks [256, 256 + EE/256): rowptr via sorted-rows boundary scan (no search).
#define PREP_BLOCKS 256
#define EDGE_BLOCKS (EE / 256)

__global__ void prep_kernel(const float* __restrict__ W, const int* __restrict__ rows) {
    if (blockIdx.x < PREP_BLOCKS) {
        const int idx = blockIdx.x * 256 + threadIdx.x;      // over N*K
        if (idx >= NN * KK) return;
        const int n = idx >> 9;          // / KK
        const int k = idx & (KK - 1);
        const float w = W[(size_t)k * NN + n];
        __nv_bfloat16 h0 = __float2bfloat16_rn(w);
        float r = w - __bfloat162float(h0);
        __nv_bfloat16 h1 = __float2bfloat16_rn(r);
        r -= __bfloat162float(h1);
        __nv_bfloat16 h2 = __float2bfloat16_rn(r);
        g_wt0[idx] = h0; g_wt1[idx] = h1; g_wt2[idx] = h2;
    } else {
        const int e = (blockIdx.x - PREP_BLOCKS) * 256 + threadIdx.x;
        if (e >= EE) return;
        const int r  = rows[e];
        const int rn = (e + 1 < EE) ? rows[e + 1] : MM;      // sentinel fills to MM
        // rowptr[i] = first edge index with rows[idx] >= i
        for (int q = r + 1; q <= rn; q++) g_rowptr[q] = e + 1;
        if (e == 0)
            for (int q = 0; q <= r; q++) g_rowptr[q] = 0;
    }
}

// ---------------- fp32 -> 3x bf16 exact truncation split (pair, packed) ----------------
// h0 = x & 0xFFFF0000 (exact bf16), r = x - h0 (exact), h1 = r & mask (exact),
// r2 = r - h1 (exact), h2 = rn(r2). Residual <= 2^-25 |x|.
__device__ __forceinline__ void split3_pair(float x0, float x1,
                                            uint32_t &u0, uint32_t &u1, uint32_t &u2) {
    const uint32_t b0 = __float_as_uint(x0), b1 = __float_as_uint(x1);
    const float h0a = __uint_as_float(b0 & 0xFFFF0000u);
    const float h0b = __uint_as_float(b1 & 0xFFFF0000u);
    const float ra = x0 - h0a, rb = x1 - h0b;
    const uint32_t ra_b = __float_as_uint(ra), rb_b = __float_as_uint(rb);
    const float h1a = __uint_as_float(ra_b & 0xFFFF0000u);
    const float h1b = __uint_as_float(rb_b & 0xFFFF0000u);
    const float r2a = ra - h1a, r2b = rb - h1b;
    u0 = __byte_perm(b0, b1, 0x7632);      // {hi16(x0), hi16(x1)}
    u1 = __byte_perm(ra_b, rb_b, 0x7632);  // {hi16(ra), hi16(rb)}
    const __nv_bfloat162 h2 = __float22bfloat162_rn(make_float2(r2a, r2b));
    u2 = *(const uint32_t*)&h2;
}

__device__ __forceinline__ void hmma16816(float c[4], const uint32_t a[4],
                                          uint32_t b0, uint32_t b1) {
    asm volatile(
        "mma.sync.aligned.m16n8k16.row.col.f32.bf16.bf16.f32 "
        "{%0,%1,%2,%3}, {%4,%5,%6,%7}, {%8,%9}, {%0,%1,%2,%3};"
        : "+f"(c[0]), "+f"(c[1]), "+f"(c[2]), "+f"(c[3])
        : "r"(a[0]), "r"(a[1]), "r"(a[2]), "r"(a[3]), "r"(b0), "r"(b1));
}

// ---------------- GEMM: g_x = feat @ W via HMMA, 3-split bf16 ----------------
// CTA tile: 128(M) x 128(N=full), K chunks of 32. 256 threads = 8 warps (4x2).
#define BK 32
#define PAD 40                      // stride 40 el = 80B = 20 banks -> conflict-free scalar LDS
#define SPLIT_EL (128 * PAD)
#define A_BYTES (3 * SPLIT_EL * 2)
#define SMEM_BYTES (2 * A_BYTES)    // 61440
#define NCH (KK / BK)

__global__ void __launch_bounds__(256, 2)
gemm_tc_kernel(const float* __restrict__ A) {
    extern __shared__ char smem[];
    __nv_bfloat16* Asm = (__nv_bfloat16*)smem;                 // [3][128][PAD]
    __nv_bfloat16* Bsm = (__nv_bfloat16*)(smem + A_BYTES);     // [3][128][PAD]

    const int tid    = threadIdx.x;
    const int lane   = tid & 31;
    const int warp   = tid >> 5;
    const int warp_m = warp >> 1;            // 0..3  -> 32 rows each
    const int warp_n = warp & 1;             // 0..1  -> 64 cols each
    const int m0     = blockIdx.x * 128;
    const int tr     = lane >> 2;            // 0..7
    const int tc2    = (lane & 3) * 2;       // 0,2,4,6

    const __nv_bfloat16* wt[3] = { g_wt0, g_wt1, g_wt2 };

    float acc[2][8][4];
    #pragma unroll
    for (int i = 0; i < 2; i++)
        #pragma unroll
        for (int j = 0; j < 8; j++)
            #pragma unroll
            for (int q = 0; q < 4; q++) acc[i][j][q] = 0.f;

    for (int ch = 0; ch < NCH; ch++) {
        // ---- A chunk: 128 x 32 fp32 -> 3 bf16 split tiles (truncation split) ----
        #pragma unroll
        for (int it = 0; it < 4; it++) {
            const int idx = tid + it * 256;        // 0..1023 float4s
            const int row = idx >> 3;
            const int c4  = idx & 7;               // float4 within 32 cols
            const int gm  = m0 + row;
            float4 v = make_float4(0.f, 0.f, 0.f, 0.f);
            if (gm < MM) v = *(const float4*)(A + (size_t)gm * KK + ch * BK + c4 * 4);
            uint32_t q0, q1, q2, r0, r1, r2;
            split3_pair(v.x, v.y, q0, q1, q2);
            split3_pair(v.z, v.w, r0, r1, r2);
            const int base = row * PAD + c4 * 4;
            *(uint2*)&Asm[0 * SPLIT_EL + base] = make_uint2(q0, r0);
            *(uint2*)&Asm[1 * SPLIT_EL + base] = make_uint2(q1, r1);
            *(uint2*)&Asm[2 * SPLIT_EL + base] = make_uint2(q2, r2);
        }
        // ---- B chunk: 3 splits x [128 n][32 k] bf16 (L2-hot) ----
        #pragma unroll
        for (int s = 0; s < 3; s++) {
            #pragma unroll
            for (int it = 0; it < 2; it++) {
                const int idx = tid + it * 256;    // 0..511 16B-pieces
                const int n   = idx >> 2;
                const int kq  = idx & 3;           // 8-bf16 group
                const float4 v = *(const float4*)(wt[s] + (size_t)n * KK + ch * BK + kq * 8);
                *(float4*)&Bsm[s * SPLIT_EL + n * PAD + kq * 8] = v;
            }
        }
        __syncthreads();

        // ---- compute: 2 k16-steps; A-fragment hoisted per a-split (scalar LDS) ----
        #pragma unroll
        for (int ks = 0; ks < 2; ks++) {
            const int k0 = ks * 16;
            #pragma unroll
            for (int i = 0; i < 3; i++) {
                const __nv_bfloat16* Ab = Asm + i * SPLIT_EL;
                uint32_t am[2][4];
                #pragma unroll
                for (int mt = 0; mt < 2; mt++) {
                    const int r = warp_m * 32 + mt * 16 + tr;
                    am[mt][0] = *(const uint32_t*)&Ab[(r    ) * PAD + k0 + tc2    ];
                    am[mt][1] = *(const uint32_t*)&Ab[(r + 8) * PAD + k0 + tc2    ];
                    am[mt][2] = *(const uint32_t*)&Ab[(r    ) * PAD + k0 + tc2 + 8];
                    am[mt][3] = *(const uint32_t*)&Ab[(r + 8) * PAD + k0 + tc2 + 8];
                }
                #pragma unroll
                for (int j = 0; j < 3 - i; j++) {   // i+j <= 2
                    const __nv_bfloat16* Bb = Bsm + j * SPLIT_EL;
                    #pragma unroll
                    for (int nt = 0; nt < 8; nt++) {
                        const int n = warp_n * 64 + nt * 8 + tr;
                        const uint32_t b0 = *(const uint32_t*)&Bb[n * PAD + k0 + tc2    ];
                        const uint32_t b1 = *(const uint32_t*)&Bb[n * PAD + k0 + tc2 + 8];
                        hmma16816(acc[0][nt], am[0], b0, b1);
                        hmma16816(acc[1][nt], am[1], b0, b1);
                    }
                }
            }
        }
        __syncthreads();
    }

    // ---- epilogue: direct STG.64 of fragment pairs ----
    #pragma unroll
    for (int mt = 0; mt < 2; mt++) {
        const int r = m0 + warp_m * 32 + mt * 16 + tr;
        #pragma unroll
        for (int nt = 0; nt < 8; nt++) {
            const int c = warp_n * 64 + nt * 8 + tc2;
            if (r < MM)
                *(float2*)&g_x[(size_t)r * NN + c] =
                    make_float2(acc[mt][nt][0], acc[mt][nt][1]);
            if (r + 8 < MM)
                *(float2*)&g_x[(size_t)(r + 8) * NN + c] =
                    make_float2(acc[mt][nt][2], acc[mt][nt][3]);
        }
    }
}

// ---------------- SpMM + multispike: warp per row, float4 lanes ----------------
__device__ __forceinline__ float mspike(float a) {
    return floorf(fminf(fmaxf(4.0f * a, 0.0f), 4.0f) + 0.5f) * 0.25f;
}

__global__ __launch_bounds__(256)
void spmm_kernel(const int* __restrict__ cols, const float* __restrict__ ew,
                 float* __restrict__ out) {
    const int wid  = threadIdx.x >> 5;
    const int lane = threadIdx.x & 31;
    const int row  = blockIdx.x * 8 + wid;
    if (row >= MM) return;
    const int s = g_rowptr[row];
    const int e = g_rowptr[row + 1];
    const float4* xb = (const float4*)g_x;

    float4 a0 = make_float4(0.f,0.f,0.f,0.f), a1 = a0, a2 = a0, a3 = a0;
    int i = s;
    for (; i + 4 <= e; i += 4) {
        const int c0 = cols[i], c1 = cols[i+1], c2 = cols[i+2], c3 = cols[i+3];
        const float w0 = ew[i], w1 = ew[i+1], w2 = ew[i+2], w3 = ew[i+3];
        const float4 v0 = xb[c0 * 32 + lane];
        const float4 v1 = xb[c1 * 32 + lane];
        const float4 v2 = xb[c2 * 32 + lane];
        const float4 v3 = xb[c3 * 32 + lane];
        a0.x = fmaf(w0, v0.x, a0.x); a0.y = fmaf(w0, v0.y, a0.y);
        a0.z = fmaf(w0, v0.z, a0.z); a0.w = fmaf(w0, v0.w, a0.w);
        a1.x = fmaf(w1, v1.x, a1.x); a1.y = fmaf(w1, v1.y, a1.y);
        a1.z = fmaf(w1, v1.z, a1.z); a1.w = fmaf(w1, v1.w, a1.w);
        a2.x = fmaf(w2, v2.x, a2.x); a2.y = fmaf(w2, v2.y, a2.y);
        a2.z = fmaf(w2, v2.z, a2.z); a2.w = fmaf(w2, v2.w, a2.w);
        a3.x = fmaf(w3, v3.x, a3.x); a3.y = fmaf(w3, v3.y, a3.y);
        a3.z = fmaf(w3, v3.z, a3.z); a3.w = fmaf(w3, v3.w, a3.w);
    }
    for (; i < e; i++) {
        const int c = cols[i];
        const float w = ew[i];
        const float4 v = xb[c * 32 + lane];
        a0.x = fmaf(w, v.x, a0.x); a0.y = fmaf(w, v.y, a0.y);
        a0.z = fmaf(w, v.z, a0.z); a0.w = fmaf(w, v.w, a0.w);
    }
    float4 t;
    t.x = mspike((a0.x + a1.x) + (a2.x + a3.x));
    t.y = mspike((a0.y + a1.y) + (a2.y + a3.y));
    t.z = mspike((a0.z + a1.z) + (a2.z + a3.z));
    t.w = mspike((a0.w + a1.w) + (a2.w + a3.w));
    ((float4*)out)[(size_t)row * 32 + lane] = t;
}

// ---------------- launch ----------------
extern "C" void kernel_launch(void* const* d_in, const int* in_sizes, int n_in,
                              void* d_out, int out_size) {
    const float* feat   = (const float*)d_in[0];
    const float* weight = (const float*)d_in[1];
    const int*   rows   = (const int*)d_in[2];
    const int*   cols   = (const int*)d_in[3];
    const float* ew     = (const float*)d_in[4];
    float* out = (float*)d_out;

    cudaFuncSetAttribute(gemm_tc_kernel,
                         cudaFuncAttributeMaxDynamicSharedMemorySize, SMEM_BYTES);

    prep_kernel<<<PREP_BLOCKS + EDGE_BLOCKS, 256>>>(weight, rows);
    gemm_tc_kernel<<<(MM + 127) / 128, 256, SMEM_BYTES>>>(feat);
    spmm_kernel<<<(MM + 7) / 8, 256>>>(cols, ew, out);
}

// round 12
// speedup vs baseline: 1.2492x; 1.0690x over previous
#include <cuda_runtime.h>
#include <cuda_bf16.h>
#include <cstdint>

#define MM 50000
#define EE 800000
#define KK 512
#define NN 128

// ---------------- device scratch (allocation-free rule) ----------------
__device__ float g_x[(size_t)MM * NN];                 // feat @ W (25.6 MB)
__device__ int   g_rowptr[MM + 1];
__device__ __nv_bfloat16 g_wt0[(size_t)NN * KK];       // W^T bf16 split 0  [n][k]
__device__ __nv_bfloat16 g_wt1[(size_t)NN * KK];       // split 1
__device__ __nv_bfloat16 g_wt2[(size_t)NN * KK];       // split 2

__device__ __forceinline__ uint32_t smem_u32(const void* p) {
    uint32_t a;
    asm("{ .reg .u64 t; cvta.to.shared.u64 t, %1; cvt.u32.u64 %0, t; }" : "=r"(a) : "l"(p));
    return a;
}

// ---------------- fused prep: W transpose+split AND rowptr boundary-scan ----------------
#define PREP_BLOCKS 256
#define EDGE_BLOCKS (EE / 256)

__global__ void prep_kernel(const float* __restrict__ W, const int* __restrict__ rows) {
    if (blockIdx.x < PREP_BLOCKS) {
        const int idx = blockIdx.x * 256 + threadIdx.x;      // over N*K
        if (idx >= NN * KK) return;
        const int n = idx >> 9;          // / KK
        const int k = idx & (KK - 1);
        const float w = W[(size_t)k * NN + n];
        __nv_bfloat16 h0 = __float2bfloat16_rn(w);
        float r = w - __bfloat162float(h0);
        __nv_bfloat16 h1 = __float2bfloat16_rn(r);
        r -= __bfloat162float(h1);
        __nv_bfloat16 h2 = __float2bfloat16_rn(r);
        g_wt0[idx] = h0; g_wt1[idx] = h1; g_wt2[idx] = h2;
    } else {
        const int e = (blockIdx.x - PREP_BLOCKS) * 256 + threadIdx.x;
        if (e >= EE) return;
        const int r  = rows[e];
        const int rn = (e + 1 < EE) ? rows[e + 1] : MM;      // sentinel fills to MM
        for (int q = r + 1; q <= rn; q++) g_rowptr[q] = e + 1;
        if (e == 0)
            for (int q = 0; q <= r; q++) g_rowptr[q] = 0;
    }
}

// ---------------- fp32 -> 3x bf16 exact truncation split (pair, packed) ----------------
__device__ __forceinline__ void split3_pair(float x0, float x1,
                                            uint32_t &u0, uint32_t &u1, uint32_t &u2) {
    const uint32_t b0 = __float_as_uint(x0), b1 = __float_as_uint(x1);
    const float h0a = __uint_as_float(b0 & 0xFFFF0000u);
    const float h0b = __uint_as_float(b1 & 0xFFFF0000u);
    const float ra = x0 - h0a, rb = x1 - h0b;
    const uint32_t ra_b = __float_as_uint(ra), rb_b = __float_as_uint(rb);
    const float h1a = __uint_as_float(ra_b & 0xFFFF0000u);
    const float h1b = __uint_as_float(rb_b & 0xFFFF0000u);
    const float r2a = ra - h1a, r2b = rb - h1b;
    u0 = __byte_perm(b0, b1, 0x7632);
    u1 = __byte_perm(ra_b, rb_b, 0x7632);
    const __nv_bfloat162 h2 = __float22bfloat162_rn(make_float2(r2a, r2b));
    u2 = *(const uint32_t*)&h2;
}

__device__ __forceinline__ void hmma16816(float c[4], const uint32_t a[4],
                                          uint32_t b0, uint32_t b1) {
    asm volatile(
        "mma.sync.aligned.m16n8k16.row.col.f32.bf16.bf16.f32 "
        "{%0,%1,%2,%3}, {%4,%5,%6,%7}, {%8,%9}, {%0,%1,%2,%3};"
        : "+f"(c[0]), "+f"(c[1]), "+f"(c[2]), "+f"(c[3])
        : "r"(a[0]), "r"(a[1]), "r"(a[2]), "r"(a[3]), "r"(b0), "r"(b1));
}

__device__ __forceinline__ void cp16(uint32_t smem_addr, const void* gptr) {
    asm volatile("cp.async.cg.shared.global [%0], [%1], 16;"
                 :: "r"(smem_addr), "l"(gptr));
}
#define CP_COMMIT() asm volatile("cp.async.commit_group;" ::: "memory")
#define CP_WAIT0()  asm volatile("cp.async.wait_group 0;" ::: "memory")

// ---------------- GEMM: double-buffered pipeline, 1 CTA/SM ----------------
// CTA tile: 128(M) x 128(N=full), K chunks of 32. 256 threads = 8 warps (4x2).
// smem layout: [A buf0][A buf1][B buf0][B buf1], each 3x128xPAD bf16 = 30720 B.
#define BK 32
#define PAD 40
#define SPLIT_EL (128 * PAD)
#define BUF_BYTES (3 * SPLIT_EL * 2)       // 30720
#define SMEM_BYTES (4 * BUF_BYTES)         // 122880
#define NCH (KK / BK)

__global__ void __launch_bounds__(256, 1)
gemm_tc_kernel(const float* __restrict__ A) {
    extern __shared__ char smem[];
    const uint32_t smem_base = smem_u32(smem);

    const int tid    = threadIdx.x;
    const int lane   = tid & 31;
    const int warp   = tid >> 5;
    const int warp_m = warp >> 1;            // 0..3  -> 32 rows each
    const int warp_n = warp & 1;             // 0..1  -> 64 cols each
    const int m0     = blockIdx.x * 128;
    const int tr     = lane >> 2;            // 0..7
    const int tc2    = (lane & 3) * 2;       // 0,2,4,6

    const __nv_bfloat16* wt[3] = { g_wt0, g_wt1, g_wt2 };

    // per-thread load coordinates
    const int pr_row = tid >> 3;             // A: rows pr_row + it*32
    const int pr_c4  = tid & 7;
    const int b_n    = (tid >> 2) & 127;     // reused with +128 offset via it
    const int b_kq   = tid & 3;

    float acc[2][8][4];
    #pragma unroll
    for (int i = 0; i < 2; i++)
        #pragma unroll
        for (int j = 0; j < 8; j++)
            #pragma unroll
            for (int q = 0; q < 4; q++) acc[i][j][q] = 0.f;

    float4 pv[4];

    // ---- helpers as lambdas ----
    auto load_A = [&](int ch) {
        #pragma unroll
        for (int it = 0; it < 4; it++) {
            const int gm = m0 + pr_row + it * 32;
            pv[it] = make_float4(0.f, 0.f, 0.f, 0.f);
            if (gm < MM) pv[it] = *(const float4*)(A + (size_t)gm * KK + ch * BK + pr_c4 * 4);
        }
    };
    auto store_A = [&](int b) {
        __nv_bfloat16* Ab = (__nv_bfloat16*)(smem + b * BUF_BYTES);
        #pragma unroll
        for (int it = 0; it < 4; it++) {
            const int row = pr_row + it * 32;
            uint32_t q0, q1, q2, r0, r1, r2;
            split3_pair(pv[it].x, pv[it].y, q0, q1, q2);
            split3_pair(pv[it].z, pv[it].w, r0, r1, r2);
            const int base = row * PAD + pr_c4 * 4;
            *(uint2*)&Ab[0 * SPLIT_EL + base] = make_uint2(q0, r0);
            *(uint2*)&Ab[1 * SPLIT_EL + base] = make_uint2(q1, r1);
            *(uint2*)&Ab[2 * SPLIT_EL + base] = make_uint2(q2, r2);
        }
    };
    auto load_B = [&](int ch, int b) {
        const uint32_t bb = smem_base + 2 * BUF_BYTES + b * BUF_BYTES;
        #pragma unroll
        for (int s = 0; s < 3; s++) {
            #pragma unroll
            for (int it = 0; it < 2; it++) {
                const int idx = tid + it * 256;          // 0..511
                const int n   = idx >> 2;
                const int kq  = idx & 3;
                cp16(bb + (uint32_t)((s * SPLIT_EL + n * PAD + kq * 8) * 2),
                     wt[s] + (size_t)n * KK + ch * BK + kq * 8);
            }
        }
        CP_COMMIT();
    };

    // ---- prologue: fill buffer 0 ----
    load_A(0);
    load_B(0, 0);
    store_A(0);
    CP_WAIT0();
    __syncthreads();

    int buf = 0;
    for (int ch = 0; ch < NCH; ch++) {
        const bool more = (ch + 1 < NCH);
        if (more) {
            load_A(ch + 1);
            load_B(ch + 1, buf ^ 1);
        }

        // ---- compute on current buffer ----
        const __nv_bfloat16* Abase = (const __nv_bfloat16*)(smem + buf * BUF_BYTES);
        const __nv_bfloat16* Bbase = (const __nv_bfloat16*)(smem + 2 * BUF_BYTES + buf * BUF_BYTES);
        #pragma unroll
        for (int ks = 0; ks < 2; ks++) {
            const int k0 = ks * 16;
            #pragma unroll
            for (int i = 0; i < 3; i++) {
                const __nv_bfloat16* Ab = Abase + i * SPLIT_EL;
                uint32_t am[2][4];
                #pragma unroll
                for (int mt = 0; mt < 2; mt++) {
                    const int r = warp_m * 32 + mt * 16 + tr;
                    am[mt][0] = *(const uint32_t*)&Ab[(r    ) * PAD + k0 + tc2    ];
                    am[mt][1] = *(const uint32_t*)&Ab[(r + 8) * PAD + k0 + tc2    ];
                    am[mt][2] = *(const uint32_t*)&Ab[(r    ) * PAD + k0 + tc2 + 8];
                    am[mt][3] = *(const uint32_t*)&Ab[(r + 8) * PAD + k0 + tc2 + 8];
                }
                #pragma unroll
                for (int j = 0; j < 3 - i; j++) {   // i+j <= 2
                    const __nv_bfloat16* Bb = Bbase + j * SPLIT_EL;
                    #pragma unroll
                    for (int nt = 0; nt < 8; nt++) {
                        const int n = warp_n * 64 + nt * 8 + tr;
                        const uint32_t b0 = *(const uint32_t*)&Bb[n * PAD + k0 + tc2    ];
                        const uint32_t b1 = *(const uint32_t*)&Bb[n * PAD + k0 + tc2 + 8];
                        hmma16816(acc[0][nt], am[0], b0, b1);
                        hmma16816(acc[1][nt], am[1], b0, b1);
                    }
                }
            }
        }

        if (more) {
            store_A(buf ^ 1);
            CP_WAIT0();
        }
        __syncthreads();
        buf ^= 1;
    }

    // ---- epilogue: direct STG.64 of fragment pairs ----
    #pragma unroll
    for (int mt = 0; mt < 2; mt++) {
        const int r = m0 + warp_m * 32 + mt * 16 + tr;
        #pragma unroll
        for (int nt = 0; nt < 8; nt++) {
            const int c = warp_n * 64 + nt * 8 + tc2;
            if (r < MM)
                *(float2*)&g_x[(size_t)r * NN + c] =
                    make_float2(acc[mt][nt][0], acc[mt][nt][1]);
            if (r + 8 < MM)
                *(float2*)&g_x[(size_t)(r + 8) * NN + c] =
                    make_float2(acc[mt][nt][2], acc[mt][nt][3]);
        }
    }
}

// ---------------- SpMM + multispike: warp per row, float4 lanes ----------------
__device__ __forceinline__ float mspike(float a) {
    return floorf(fminf(fmaxf(4.0f * a, 0.0f), 4.0f) + 0.5f) * 0.25f;
}

__global__ __launch_bounds__(256)
void spmm_kernel(const int* __restrict__ cols, const float* __restrict__ ew,
                 float* __restrict__ out) {
    const int wid  = threadIdx.x >> 5;
    const int lane = threadIdx.x & 31;
    const int row  = blockIdx.x * 8 + wid;
    if (row >= MM) return;
    const int s = g_rowptr[row];
    const int e = g_rowptr[row + 1];
    const float4* xb = (const float4*)g_x;

    float4 a0 = make_float4(0.f,0.f,0.f,0.f), a1 = a0, a2 = a0, a3 = a0;
    int i = s;
    for (; i + 4 <= e; i += 4) {
        const int c0 = cols[i], c1 = cols[i+1], c2 = cols[i+2], c3 = cols[i+3];
        const float w0 = ew[i], w1 = ew[i+1], w2 = ew[i+2], w3 = ew[i+3];
        const float4 v0 = xb[c0 * 32 + lane];
        const float4 v1 = xb[c1 * 32 + lane];
        const float4 v2 = xb[c2 * 32 + lane];
        const float4 v3 = xb[c3 * 32 + lane];
        a0.x = fmaf(w0, v0.x, a0.x); a0.y = fmaf(w0, v0.y, a0.y);
        a0.z = fmaf(w0, v0.z, a0.z); a0.w = fmaf(w0, v0.w, a0.w);
        a1.x = fmaf(w1, v1.x, a1.x); a1.y = fmaf(w1, v1.y, a1.y);
        a1.z = fmaf(w1, v1.z, a1.z); a1.w = fmaf(w1, v1.w, a1.w);
        a2.x = fmaf(w2, v2.x, a2.x); a2.y = fmaf(w2, v2.y, a2.y);
        a2.z = fmaf(w2, v2.z, a2.z); a2.w = fmaf(w2, v2.w, a2.w);
        a3.x = fmaf(w3, v3.x, a3.x); a3.y = fmaf(w3, v3.y, a3.y);
        a3.z = fmaf(w3, v3.z, a3.z); a3.w = fmaf(w3, v3.w, a3.w);
    }
    for (; i < e; i++) {
        const int c = cols[i];
        const float w = ew[i];
        const float4 v = xb[c * 32 + lane];
        a0.x = fmaf(w, v.x, a0.x); a0.y = fmaf(w, v.y, a0.y);
        a0.z = fmaf(w, v.z, a0.z); a0.w = fmaf(w, v.w, a0.w);
    }
    float4 t;
    t.x = mspike((a0.x + a1.x) + (a2.x + a3.x));
    t.y = mspike((a0.y + a1.y) + (a2.y + a3.y));
    t.z = mspike((a0.z + a1.z) + (a2.z + a3.z));
    t.w = mspike((a0.w + a1.w) + (a2.w + a3.w));
    ((float4*)out)[(size_t)row * 32 + lane] = t;
}

// ---------------- launch ----------------
extern "C" void kernel_launch(void* const* d_in, const int* in_sizes, int n_in,
                              void* d_out, int out_size) {
    const float* feat   = (const float*)d_in[0];
    const float* weight = (const float*)d_in[1];
    const int*   rows   = (const int*)d_in[2];
    const int*   cols   = (const int*)d_in[3];
    const float* ew     = (const float*)d_in[4];
    float* out = (float*)d_out;

    cudaFuncSetAttribute(gemm_tc_kernel,
                         cudaFuncAttributeMaxDynamicSharedMemorySize, SMEM_BYTES);

    prep_kernel<<<PREP_BLOCKS + EDGE_BLOCKS, 256>>>(weight, rows);
    gemm_tc_kernel<<<(MM + 127) / 128, 256, SMEM_BYTES>>>(feat);
    spmm_kernel<<<(MM + 7) / 8, 256>>>(cols, ew, out);
}

// round 13
// speedup vs baseline: 1.2497x; 1.0004x over previous
#include <cuda_runtime.h>
#include <cuda_bf16.h>
#include <cstdint>

#define MM 50000
#define EE 800000
#define KK 512
#define NN 128

// ---------------- device scratch (allocation-free rule) ----------------
__device__ float g_x[(size_t)MM * NN];                 // feat @ W (25.6 MB)
__device__ int   g_rowptr[MM + 1];
__device__ __nv_bfloat16 g_wt0[(size_t)NN * KK];       // W^T bf16 split 0  [n][k]
__device__ __nv_bfloat16 g_wt1[(size_t)NN * KK];       // split 1
__device__ __nv_bfloat16 g_wt2[(size_t)NN * KK];       // split 2

__device__ __forceinline__ uint32_t smem_u32(const void* p) {
    uint32_t a;
    asm("{ .reg .u64 t; cvta.to.shared.u64 t, %1; cvt.u32.u64 %0, t; }" : "=r"(a) : "l"(p));
    return a;
}

// ---------------- fused prep: W transpose+split AND rowptr boundary-scan ----------------
#define PREP_BLOCKS 256
#define EDGE_BLOCKS (EE / 256)

__global__ void prep_kernel(const float* __restrict__ W, const int* __restrict__ rows) {
    if (blockIdx.x < PREP_BLOCKS) {
        const int idx = blockIdx.x * 256 + threadIdx.x;      // over N*K
        if (idx >= NN * KK) return;
        const int n = idx >> 9;          // / KK
        const int k = idx & (KK - 1);
        const float w = W[(size_t)k * NN + n];
        __nv_bfloat16 h0 = __float2bfloat16_rn(w);
        float r = w - __bfloat162float(h0);
        __nv_bfloat16 h1 = __float2bfloat16_rn(r);
        r -= __bfloat162float(h1);
        __nv_bfloat16 h2 = __float2bfloat16_rn(r);
        g_wt0[idx] = h0; g_wt1[idx] = h1; g_wt2[idx] = h2;
    } else {
        const int e = (blockIdx.x - PREP_BLOCKS) * 256 + threadIdx.x;
        if (e >= EE) return;
        const int r  = rows[e];
        const int rn = (e + 1 < EE) ? rows[e + 1] : MM;      // sentinel fills to MM
        for (int q = r + 1; q <= rn; q++) g_rowptr[q] = e + 1;
        if (e == 0)
            for (int q = 0; q <= r; q++) g_rowptr[q] = 0;
    }
}

// ---------------- fp32 -> 3x bf16 exact truncation split (pair, packed) ----------------
__device__ __forceinline__ void split3_pair(float x0, float x1,
                                            uint32_t &u0, uint32_t &u1, uint32_t &u2) {
    const uint32_t b0 = __float_as_uint(x0), b1 = __float_as_uint(x1);
    const float h0a = __uint_as_float(b0 & 0xFFFF0000u);
    const float h0b = __uint_as_float(b1 & 0xFFFF0000u);
    const float ra = x0 - h0a, rb = x1 - h0b;
    const uint32_t ra_b = __float_as_uint(ra), rb_b = __float_as_uint(rb);
    const float h1a = __uint_as_float(ra_b & 0xFFFF0000u);
    const float h1b = __uint_as_float(rb_b & 0xFFFF0000u);
    const float r2a = ra - h1a, r2b = rb - h1b;
    u0 = __byte_perm(b0, b1, 0x7632);
    u1 = __byte_perm(ra_b, rb_b, 0x7632);
    const __nv_bfloat162 h2 = __float22bfloat162_rn(make_float2(r2a, r2b));
    u2 = *(const uint32_t*)&h2;
}

__device__ __forceinline__ void hmma16816(float c[4], const uint32_t a[4],
                                          uint32_t b0, uint32_t b1) {
    asm volatile(
        "mma.sync.aligned.m16n8k16.row.col.f32.bf16.bf16.f32 "
        "{%0,%1,%2,%3}, {%4,%5,%6,%7}, {%8,%9}, {%0,%1,%2,%3};"
        : "+f"(c[0]), "+f"(c[1]), "+f"(c[2]), "+f"(c[3])
        : "r"(a[0]), "r"(a[1]), "r"(a[2]), "r"(a[3]), "r"(b0), "r"(b1));
}

__device__ __forceinline__ void cp16(uint32_t smem_addr, const void* gptr) {
    asm volatile("cp.async.cg.shared.global [%0], [%1], 16;"
                 :: "r"(smem_addr), "l"(gptr));
}
#define CP_COMMIT() asm volatile("cp.async.commit_group;" ::: "memory")
#define CP_WAIT0()  asm volatile("cp.async.wait_group 0;" ::: "memory")

// ---------------- GEMM: double-buffered pipeline, BK=64, 1 CTA/SM ----------------
// CTA tile: 128(M) x 128(N=full), K chunks of 64 -> 8 chunks. 256 threads = 8 warps (4x2).
// smem: [A buf0][A buf1][B buf0][B buf1], each 3 x 128 x PAD(72) bf16 = 55296 B.
#define BK 64
#define PAD 72                       // 144 B row stride = 36 words -> conflict-free patterns
#define SPLIT_EL (128 * PAD)
#define BUF_BYTES (3 * SPLIT_EL * 2) // 55296
#define SMEM_BYTES (4 * BUF_BYTES)   // 221184
#define NCH (KK / BK)                // 8

__global__ void __launch_bounds__(256, 1)
gemm_tc_kernel(const float* __restrict__ A) {
    extern __shared__ char smem[];
    const uint32_t smem_base = smem_u32(smem);

    const int tid    = threadIdx.x;
    const int lane   = tid & 31;
    const int warp   = tid >> 5;
    const int warp_m = warp >> 1;            // 0..3  -> 32 rows each
    const int warp_n = warp & 1;             // 0..1  -> 64 cols each
    const int m0     = blockIdx.x * 128;
    const int tr     = lane >> 2;            // 0..7
    const int tc2    = (lane & 3) * 2;       // 0,2,4,6

    const __nv_bfloat16* wt[3] = { g_wt0, g_wt1, g_wt2 };

    // A load coords: 8 float4/thread; it covers 16 rows per step
    const int pr_row = tid >> 4;             // 0..15
    const int pr_c4  = tid & 15;             // 0..15 -> col = pr_c4*4 (0..60)

    float acc[2][8][4];
    #pragma unroll
    for (int i = 0; i < 2; i++)
        #pragma unroll
        for (int j = 0; j < 8; j++)
            #pragma unroll
            for (int q = 0; q < 4; q++) acc[i][j][q] = 0.f;

    float4 pv[8];

    auto load_A = [&](int ch) {
        #pragma unroll
        for (int it = 0; it < 8; it++) {
            const int gm = m0 + pr_row + it * 16;
            pv[it] = make_float4(0.f, 0.f, 0.f, 0.f);
            if (gm < MM) pv[it] = *(const float4*)(A + (size_t)gm * KK + ch * BK + pr_c4 * 4);
        }
    };
    auto store_A = [&](int b) {
        __nv_bfloat16* Ab = (__nv_bfloat16*)(smem + b * BUF_BYTES);
        #pragma unroll
        for (int it = 0; it < 8; it++) {
            const int row = pr_row + it * 16;
            uint32_t q0, q1, q2, r0, r1, r2;
            split3_pair(pv[it].x, pv[it].y, q0, q1, q2);
            split3_pair(pv[it].z, pv[it].w, r0, r1, r2);
            const int base = row * PAD + pr_c4 * 4;
            *(uint2*)&Ab[0 * SPLIT_EL + base] = make_uint2(q0, r0);
            *(uint2*)&Ab[1 * SPLIT_EL + base] = make_uint2(q1, r1);
            *(uint2*)&Ab[2 * SPLIT_EL + base] = make_uint2(q2, r2);
        }
    };
    auto load_B = [&](int ch, int b) {
        const uint32_t bb = smem_base + 2 * BUF_BYTES + b * BUF_BYTES;
        #pragma unroll
        for (int s = 0; s < 3; s++) {
            #pragma unroll
            for (int it = 0; it < 4; it++) {
                const int idx = tid + it * 256;          // 0..1023 16B-pieces
                const int n   = idx >> 3;                // 0..127
                const int kq  = idx & 7;                 // 8 x 16B per 64-el row
                cp16(bb + (uint32_t)((s * SPLIT_EL + n * PAD + kq * 8) * 2),
                     wt[s] + (size_t)n * KK + ch * BK + kq * 8);
            }
        }
        CP_COMMIT();
    };

    // ---- prologue: fill buffer 0 ----
    load_A(0);
    load_B(0, 0);
    store_A(0);
    CP_WAIT0();
    __syncthreads();

    int buf = 0;
    for (int ch = 0; ch < NCH; ch++) {
        const bool more = (ch + 1 < NCH);
        if (more) {
            load_A(ch + 1);
            load_B(ch + 1, buf ^ 1);
        }

        // ---- compute on current buffer: 4 k16-steps x 6 products ----
        const __nv_bfloat16* Abase = (const __nv_bfloat16*)(smem + buf * BUF_BYTES);
        const __nv_bfloat16* Bbase = (const __nv_bfloat16*)(smem + 2 * BUF_BYTES + buf * BUF_BYTES);
        #pragma unroll
        for (int ks = 0; ks < 4; ks++) {
            const int k0 = ks * 16;
            #pragma unroll
            for (int i = 0; i < 3; i++) {
                const __nv_bfloat16* Ab = Abase + i * SPLIT_EL;
                uint32_t am[2][4];
                #pragma unroll
                for (int mt = 0; mt < 2; mt++) {
                    const int r = warp_m * 32 + mt * 16 + tr;
                    am[mt][0] = *(const uint32_t*)&Ab[(r    ) * PAD + k0 + tc2    ];
                    am[mt][1] = *(const uint32_t*)&Ab[(r + 8) * PAD + k0 + tc2    ];
                    am[mt][2] = *(const uint32_t*)&Ab[(r    ) * PAD + k0 + tc2 + 8];
                    am[mt][3] = *(const uint32_t*)&Ab[(r + 8) * PAD + k0 + tc2 + 8];
                }
                #pragma unroll
                for (int j = 0; j < 3 - i; j++) {   // i+j <= 2
                    const __nv_bfloat16* Bb = Bbase + j * SPLIT_EL;
                    #pragma unroll
                    for (int nt = 0; nt < 8; nt++) {
                        const int n = warp_n * 64 + nt * 8 + tr;
                        const uint32_t b0 = *(const uint32_t*)&Bb[n * PAD + k0 + tc2    ];
                        const uint32_t b1 = *(const uint32_t*)&Bb[n * PAD + k0 + tc2 + 8];
                        hmma16816(acc[0][nt], am[0], b0, b1);
                        hmma16816(acc[1][nt], am[1], b0, b1);
                    }
                }
            }
        }

        if (more) {
            store_A(buf ^ 1);
            CP_WAIT0();
        }
        __syncthreads();
        buf ^= 1;
    }

    // ---- epilogue: direct STG.64 of fragment pairs ----
    #pragma unroll
    for (int mt = 0; mt < 2; mt++) {
        const int r = m0 + warp_m * 32 + mt * 16 + tr;
        #pragma unroll
        for (int nt = 0; nt < 8; nt++) {
            const int c = warp_n * 64 + nt * 8 + tc2;
            if (r < MM)
                *(float2*)&g_x[(size_t)r * NN + c] =
                    make_float2(acc[mt][nt][0], acc[mt][nt][1]);
            if (r + 8 < MM)
                *(float2*)&g_x[(size_t)(r + 8) * NN + c] =
                    make_float2(acc[mt][nt][2], acc[mt][nt][3]);
        }
    }
}

// ---------------- SpMM + multispike: warp per row, float4 lanes ----------------
__device__ __forceinline__ float mspike(float a) {
    return floorf(fminf(fmaxf(4.0f * a, 0.0f), 4.0f) + 0.5f) * 0.25f;
}

__global__ __launch_bounds__(256)
void spmm_kernel(const int* __restrict__ cols, const float* __restrict__ ew,
                 float* __restrict__ out) {
    const int wid  = threadIdx.x >> 5;
    const int lane = threadIdx.x & 31;
    const int row  = blockIdx.x * 8 + wid;
    if (row >= MM) return;
    const int s = g_rowptr[row];
    const int e = g_rowptr[row + 1];
    const float4* xb = (const float4*)g_x;

    float4 a0 = make_float4(0.f,0.f,0.f,0.f), a1 = a0, a2 = a0, a3 = a0;
    int i = s;
    for (; i + 4 <= e; i += 4) {
        const int c0 = cols[i], c1 = cols[i+1], c2 = cols[i+2], c3 = cols[i+3];
        const float w0 = ew[i], w1 = ew[i+1], w2 = ew[i+2], w3 = ew[i+3];
        const float4 v0 = xb[c0 * 32 + lane];
        const float4 v1 = xb[c1 * 32 + lane];
        const float4 v2 = xb[c2 * 32 + lane];
        const float4 v3 = xb[c3 * 32 + lane];
        a0.x = fmaf(w0, v0.x, a0.x); a0.y = fmaf(w0, v0.y, a0.y);
        a0.z = fmaf(w0, v0.z, a0.z); a0.w = fmaf(w0, v0.w, a0.w);
        a1.x = fmaf(w1, v1.x, a1.x); a1.y = fmaf(w1, v1.y, a1.y);
        a1.z = fmaf(w1, v1.z, a1.z); a1.w = fmaf(w1, v1.w, a1.w);
        a2.x = fmaf(w2, v2.x, a2.x); a2.y = fmaf(w2, v2.y, a2.y);
        a2.z = fmaf(w2, v2.z, a2.z); a2.w = fmaf(w2, v2.w, a2.w);
        a3.x = fmaf(w3, v3.x, a3.x); a3.y = fmaf(w3, v3.y, a3.y);
        a3.z = fmaf(w3, v3.z, a3.z); a3.w = fmaf(w3, v3.w, a3.w);
    }
    for (; i < e; i++) {
        const int c = cols[i];
        const float w = ew[i];
        const float4 v = xb[c * 32 + lane];
        a0.x = fmaf(w, v.x, a0.x); a0.y = fmaf(w, v.y, a0.y);
        a0.z = fmaf(w, v.z, a0.z); a0.w = fmaf(w, v.w, a0.w);
    }
    float4 t;
    t.x = mspike((a0.x + a1.x) + (a2.x + a3.x));
    t.y = mspike((a0.y + a1.y) + (a2.y + a3.y));
    t.z = mspike((a0.z + a1.z) + (a2.z + a3.z));
    t.w = mspike((a0.w + a1.w) + (a2.w + a3.w));
    ((float4*)out)[(size_t)row * 32 + lane] = t;
}

// ---------------- launch ----------------
extern "C" void kernel_launch(void* const* d_in, const int* in_sizes, int n_in,
                              void* d_out, int out_size) {
    const float* feat   = (const float*)d_in[0];
    const float* weight = (const float*)d_in[1];
    const int*   rows   = (const int*)d_in[2];
    const int*   cols   = (const int*)d_in[3];
    const float* ew     = (const float*)d_in[4];
    float* out = (float*)d_out;

    cudaFuncSetAttribute(gemm_tc_kernel,
                         cudaFuncAttributeMaxDynamicSharedMemorySize, SMEM_BYTES);

    prep_kernel<<<PREP_BLOCKS + EDGE_BLOCKS, 256>>>(weight, rows);
    gemm_tc_kernel<<<(MM + 127) / 128, 256, SMEM_BYTES>>>(feat);
    spmm_kernel<<<(MM + 7) / 8, 256>>>(cols, ew, out);
}